// round 3
// baseline (speedup 1.0000x reference)
#include <cuda_runtime.h>

// PixelWiseNet: out[h,w] = bias + sum_{c,k} p_a[c,k] * relu(x[c,h,w]*rowsum(M[c]) + bias_c[c] - p_t[c,k])
// C=3, H=W=1024, K=16. Output [1024,1024] f32.
//
// Restructured:  a*relu(s-t) = a*max(s,t) - a*t
//                a*max(x*scale+bc, t) = (a*|scale|)*max(x*sgn, (t-bc)/|scale|) + a*bc
// => out = CONST + sum_{c,k} a'_{ck} * max(u_c, t'_{ck}),  u_c = x_c * sgn(scale_c)
//    CONST = bias + sum_{c,k} a_{ck}*(bc_c - t_{ck})
// Per pixel: 48 FMNMX (alu pipe) + 48 FFMA (fma pipe) + 3 FMUL. Balanced pipes.

#define C 3
#define K 16
#define HW (1024 * 1024)
#define N4 (HW / 4)              // float4 per channel plane = 262144
#define THREADS 256
#define F4_PER_THREAD 2          // 8 pixels per thread
#define BLOCKS (N4 / (THREADS * F4_PER_THREAD))  // 512

__global__ __launch_bounds__(THREADS)
void pixelwise_kernel(const float4* __restrict__ x,
                      const float* __restrict__ M,
                      const float* __restrict__ p_a,
                      const float* __restrict__ p_t,
                      const float* __restrict__ bias_c,
                      const float* __restrict__ bias,
                      float4* __restrict__ out) {
    __shared__ float2 sh_at[C * K];   // (a', t') interleaved -> one LDS.64 per hinge
    __shared__ float  sh_xsign[C];
    __shared__ float  sh_const;
    __shared__ float  sh_partial[64];

    int tid = threadIdx.x;

    // ---- per-block parameter transform (48 threads) ----
    if (tid < C * K) {
        int c = tid / K;
        float scale = M[c * 3 + 0] + M[c * 3 + 1] + M[c * 3 + 2];
        float sa = fabsf(scale);
        float a = p_a[tid], t = p_t[tid], bc = bias_c[c];
        float ap, tp, cst;
        if (sa > 0.0f) {
            ap  = a * sa;
            tp  = (t - bc) / sa;
            cst = a * (bc - t);
        } else {
            // s == bc (constant): contribution a*(max(bc,t)-t), no pixel dependence
            ap = 0.0f; tp = 0.0f;
            cst = a * (fmaxf(bc, t) - t);
        }
        sh_at[tid] = make_float2(ap, tp);
        sh_partial[tid] = cst;
        if (tid < C) sh_xsign[tid] = (scale >= 0.0f) ? 1.0f : -1.0f;
    } else if (tid < 64) {
        sh_partial[tid] = 0.0f;
    }
    __syncthreads();
    if (tid < 32) {
        float v = sh_partial[tid] + sh_partial[tid + 32];
        #pragma unroll
        for (int o = 16; o; o >>= 1) v += __shfl_xor_sync(0xffffffffu, v, o);
        if (tid == 0) sh_const = v + bias[0];
    }
    __syncthreads();

    // ---- main loop: 8 pixels (2 float4) per thread ----
    int base = blockIdx.x * (THREADS * F4_PER_THREAD) + tid;   // first float4 index
    float b = sh_const;
    float4 acc0 = make_float4(b, b, b, b);
    float4 acc1 = make_float4(b, b, b, b);

    #pragma unroll
    for (int c = 0; c < C; c++) {
        float xs = sh_xsign[c];
        float4 v0 = x[c * N4 + base];
        float4 v1 = x[c * N4 + base + THREADS];
        float u0x = v0.x * xs, u0y = v0.y * xs, u0z = v0.z * xs, u0w = v0.w * xs;
        float u1x = v1.x * xs, u1y = v1.y * xs, u1z = v1.z * xs, u1w = v1.w * xs;
        #pragma unroll
        for (int k = 0; k < K; k++) {
            float2 p = sh_at[c * K + k];
            acc0.x = fmaf(p.x, fmaxf(u0x, p.y), acc0.x);
            acc0.y = fmaf(p.x, fmaxf(u0y, p.y), acc0.y);
            acc0.z = fmaf(p.x, fmaxf(u0z, p.y), acc0.z);
            acc0.w = fmaf(p.x, fmaxf(u0w, p.y), acc0.w);
            acc1.x = fmaf(p.x, fmaxf(u1x, p.y), acc1.x);
            acc1.y = fmaf(p.x, fmaxf(u1y, p.y), acc1.y);
            acc1.z = fmaf(p.x, fmaxf(u1z, p.y), acc1.z);
            acc1.w = fmaf(p.x, fmaxf(u1w, p.y), acc1.w);
        }
    }

    out[base] = acc0;
    out[base + THREADS] = acc1;
}

extern "C" void kernel_launch(void* const* d_in, const int* in_sizes, int n_in,
                              void* d_out, int out_size) {
    const float4* x      = (const float4*)d_in[0];
    const float*  M      = (const float*)d_in[1];
    const float*  p_a    = (const float*)d_in[2];
    const float*  p_t    = (const float*)d_in[3];
    const float*  bias_c = (const float*)d_in[4];
    const float*  bias   = (const float*)d_in[5];
    float4* out = (float4*)d_out;

    pixelwise_kernel<<<BLOCKS, THREADS>>>(x, M, p_a, p_t, bias_c, bias, out);
}